// round 16
// baseline (speedup 1.0000x reference)
#include <cuda_runtime.h>
#include <cuda_fp16.h>
#include <math.h>
#include <stdint.h>

// ---------------------------------------------------------------------------
// UPGAT layer.  N=100000, R=500, D=512, E=150000, B=4096.
// GEMMs: fp16 single-pass mma.sync, CTA 128x128, 8 warps (32x64), BK=64,
// 3-stage cp.async, 2 CTAs/SM.  Cedge GEMM fuses the e0h[dst]*relh[rel]
// gather into its A-staging (st.shared PTX store).  2-stream overlap.
// ---------------------------------------------------------------------------

#define MAX_N 100000
#define MAX_E 150000
#define MAX_R 500
#define MAX_D 512

__device__ float g_entn [(size_t)MAX_N * MAX_D];
__device__ float g_reln [(size_t)MAX_R * MAX_D];

__device__ __half g_Epreh [(size_t)MAX_N * MAX_D];
__device__ __half g_Cbaseh[(size_t)MAX_N * MAX_D];
__device__ __half g_Cedgeh[(size_t)MAX_E * MAX_D];

__device__ int g_cnt [MAX_N];
__device__ int g_off [MAX_N + 1];
__device__ int g_cur [MAX_N];
__device__ int g_eidx[MAX_E];
__device__ int g_bsum[128];

__device__ __half g_e0h[(size_t)MAX_N * MAX_D];
__device__ __half g_egh[(size_t)MAX_N * MAX_D];
__device__ __half g_relh[(size_t)MAX_R * MAX_D];
__device__ __half g_w1h[MAX_D * MAX_D];
__device__ __half g_weth[MAX_D * MAX_D];

// ---------------------------------------------------------------------------
// helpers
// ---------------------------------------------------------------------------
__device__ __forceinline__ uint32_t smem_to_u32(const void* smem_ptr) {
    uint32_t addr;
    asm("{ .reg .u64 tmp; cvta.to.shared.u64 tmp, %1; cvt.u32.u64 %0, tmp; }"
        : "=r"(addr) : "l"(smem_ptr));
    return addr;
}
__device__ __forceinline__ void ldsm4(uint32_t addr, uint32_t& r0, uint32_t& r1,
                                      uint32_t& r2, uint32_t& r3) {
    asm volatile("ldmatrix.sync.aligned.m8n8.x4.shared.b16 {%0,%1,%2,%3}, [%4];"
                 : "=r"(r0), "=r"(r1), "=r"(r2), "=r"(r3) : "r"(addr));
}
__device__ __forceinline__ void mma_fp16(float* d, const uint32_t* a, const uint32_t* b) {
    asm volatile(
        "mma.sync.aligned.m16n8k16.row.col.f32.f16.f16.f32 "
        "{%0,%1,%2,%3}, {%4,%5,%6,%7}, {%8,%9}, {%0,%1,%2,%3};"
        : "+f"(d[0]), "+f"(d[1]), "+f"(d[2]), "+f"(d[3])
        : "r"(a[0]), "r"(a[1]), "r"(a[2]), "r"(a[3]), "r"(b[0]), "r"(b[1]));
}
__device__ __forceinline__ void cp16(uint32_t dst, const void* src, bool pred) {
    int sz = pred ? 16 : 0;
    asm volatile("cp.async.cg.shared.global [%0], [%1], 16, %2;"
                 :: "r"(dst), "l"(src), "r"(sz) : "memory");
}
__device__ __forceinline__ void sts16(uint32_t addr, uint4 v) {
    asm volatile("st.shared.v4.b32 [%0], {%1,%2,%3,%4};"
                 :: "r"(addr), "r"(v.x), "r"(v.y), "r"(v.z), "r"(v.w) : "memory");
}
__device__ __forceinline__ uint32_t pkh(__half a, __half b) {
    __half2 t = __halves2half2(a, b);
    return *reinterpret_cast<uint32_t*>(&t);
}
__device__ __forceinline__ uint2 h4(float4 v) {
    return make_uint2(pkh(__float2half_rn(v.x), __float2half_rn(v.y)),
                      pkh(__float2half_rn(v.z), __float2half_rn(v.w)));
}
__device__ __forceinline__ float4 f4ofh(uint2 u) {
    __half2* h2 = (__half2*)&u;
    float2 a = __half22float2(h2[0]);
    float2 b = __half22float2(h2[1]);
    return make_float4(a.x, a.y, b.x, b.y);
}
__device__ __forceinline__ float tanha(float x) {
    float y;
    asm("tanh.approx.f32 %0, %1;" : "=f"(y) : "f"(x));
    return y;
}
__device__ __forceinline__ uint4 hmul8(uint4 a, uint4 b) {
    __half2* ah = (__half2*)&a;
    __half2* bh = (__half2*)&b;
    uint4 r;
    __half2* rh = (__half2*)&r;
    rh[0] = __hmul2(ah[0], bh[0]);
    rh[1] = __hmul2(ah[1], bh[1]);
    rh[2] = __hmul2(ah[2], bh[2]);
    rh[3] = __hmul2(ah[3], bh[3]);
    return r;
}

// ---------------------------------------------------------------------------
__global__ void zero_int(int* __restrict__ p, int n) {
    int i = blockIdx.x * blockDim.x + threadIdx.x;
    if (i < n) p[i] = 0;
}

__global__ void normalize_split(const float* __restrict__ in, const float* __restrict__ g0,
                                __half* __restrict__ e0h, __half* __restrict__ egh,
                                int M, int D) {
    int warp = (blockIdx.x * blockDim.x + threadIdx.x) >> 5;
    int lane = threadIdx.x & 31;
    if (warp >= M) return;
    const float4* ip = (const float4*)(in + (size_t)warp * D);
    const float4* gp = (const float4*)g0;
    int nv = D >> 2;
    float s = 0.f;
    for (int i = lane; i < nv; i += 32) {
        float4 v = ip[i];
        s += v.x * v.x + v.y * v.y + v.z * v.z + v.w * v.w;
    }
    #pragma unroll
    for (int o = 16; o; o >>= 1) s += __shfl_xor_sync(0xFFFFFFFFu, s, o);
    float inv = 1.f / fmaxf(sqrtf(s), 1e-12f);
    size_t rbase = (size_t)warp * D;
    for (int i = lane; i < nv; i += 32) {
        float4 v = ip[i];
        float4 n = make_float4(v.x * inv, v.y * inv, v.z * inv, v.w * inv);
        *(uint2*)(e0h + rbase + i * 4) = h4(n);
        float4 g = gp[i];
        *(uint2*)(egh + rbase + i * 4) =
            h4(make_float4(n.x * g.x, n.y * g.y, n.z * g.z, n.w * g.w));
    }
}

__global__ void split_weights(const float* __restrict__ W1, const float* __restrict__ WE,
                              const float* __restrict__ rel,
                              __half* __restrict__ w1h, __half* __restrict__ weth,
                              __half* __restrict__ relh, int D, int RD) {
    int i = blockIdx.x * blockDim.x + threadIdx.x;
    int tot = D * D;
    if (i < tot) {
        w1h[i] = __float2half_rn(W1[i]);
        int k = i / D, j = i % D;
        weth[(size_t)j * D + k] = __float2half_rn(WE[i]);
    }
    if (i < RD) relh[i] = __float2half_rn(rel[i]);
}

__global__ void count_deg(const int* __restrict__ srcs, int* __restrict__ cnt, int E) {
    int e = blockIdx.x * blockDim.x + threadIdx.x;
    if (e < E) atomicAdd(&cnt[srcs[e]], 1);
}
__global__ void scan1(const int* __restrict__ cnt, int* __restrict__ off,
                      int* __restrict__ bsum, int N) {
    __shared__ int sm[1024];
    int tid = threadIdx.x;
    int i = blockIdx.x * 1024 + tid;
    int v = (i < N) ? cnt[i] : 0;
    sm[tid] = v;
    __syncthreads();
    #pragma unroll
    for (int d = 1; d < 1024; d <<= 1) {
        int t = (tid >= d) ? sm[tid - d] : 0;
        __syncthreads();
        sm[tid] += t;
        __syncthreads();
    }
    if (i < N) off[i] = sm[tid] - v;
    if (tid == 1023) bsum[blockIdx.x] = sm[1023];
}
__global__ void scan3b(int* __restrict__ off, int* __restrict__ cur,
                       const int* __restrict__ bsum, int nblk, int N, int E) {
    __shared__ int sb[128];
    int tid = threadIdx.x;
    if (tid < 128) sb[tid] = (tid < nblk) ? bsum[tid] : 0;
    __syncthreads();
    #pragma unroll
    for (int d = 1; d < 128; d <<= 1) {
        int t = (tid < 128 && tid >= d) ? sb[tid - d] : 0;
        __syncthreads();
        if (tid < 128) sb[tid] += t;
        __syncthreads();
    }
    int i = blockIdx.x * blockDim.x + tid;
    if (i < N) {
        int bi = i >> 10;
        int pre = (bi == 0) ? 0 : sb[bi - 1];
        int o = off[i] + pre;
        off[i] = o;
        cur[i] = o;
    }
    if (i == 0) off[N] = E;
}
__global__ void fill_eidx(const int* __restrict__ srcs, int* __restrict__ cur,
                          int* __restrict__ eidx, int E) {
    int e = blockIdx.x * blockDim.x + threadIdx.x;
    if (e < E) {
        int pos = atomicAdd(&cur[srcs[e]], 1);
        eidx[pos] = e;
    }
}

__global__ void node_aggregate(const __half* __restrict__ e0h, const __half* __restrict__ Cbh,
                               const __half* __restrict__ Ceh, const __half* __restrict__ Epreh,
                               const float* __restrict__ Wa,
                               const int* __restrict__ off,
                               float* __restrict__ entnew, int N, int D) {
    __shared__ float waS[512];
    for (int i = threadIdx.x; i < D; i += blockDim.x) waS[i] = Wa[i];
    __syncthreads();

    int warp = (blockIdx.x * blockDim.x + threadIdx.x) >> 5;
    int lane = threadIdx.x & 31;
    if (warp >= N) return;
    int o0 = off[warp], o1 = off[warp + 1];
    int deg = o1 - o0;

    const uint2* ep = (const uint2*)(e0h + (size_t)warp * D);
    const uint2* cbp = (const uint2*)(Cbh + (size_t)warp * D);
    const float4* wp = (const float4*)waS;

    float4 ew[4], acc[4];
    float sb = 0.f;
    #pragma unroll
    for (int i = 0; i < 4; i++) {
        int ii = lane + i * 32;
        float4 e = f4ofh(ep[ii]);
        float4 w = wp[ii];
        ew[i] = make_float4(e.x * w.x, e.y * w.y, e.z * w.z, e.w * w.w);
        float4 c = f4ofh(cbp[ii]);
        acc[i] = c;
        sb += ew[i].x * tanha(c.x) + ew[i].y * tanha(c.y) +
              ew[i].z * tanha(c.z) + ew[i].w * tanha(c.w);
    }
    #pragma unroll
    for (int o = 16; o; o >>= 1) sb += __shfl_xor_sync(0xFFFFFFFFu, sb, o);
    float lb = sb > 0.f ? sb : 0.2f * sb;
    float ab = expf(-lb);
    float coef = (deg > 0) ? ab : 0.f;
    float den = coef;
    #pragma unroll
    for (int i = 0; i < 4; i++) {
        acc[i].x *= coef; acc[i].y *= coef; acc[i].z *= coef; acc[i].w *= coef;
    }

    uint2 nxt[4];
    if (deg > 0) {
        const uint2* cp = (const uint2*)(Ceh + (size_t)o0 * D);
        #pragma unroll
        for (int i = 0; i < 4; i++) nxt[i] = cp[lane + i * 32];
    }
    for (int j = o0; j < o1; j++) {
        uint2 cur4[4];
        #pragma unroll
        for (int i = 0; i < 4; i++) cur4[i] = nxt[i];
        if (j + 1 < o1) {
            const uint2* cp = (const uint2*)(Ceh + (size_t)(j + 1) * D);
            #pragma unroll
            for (int i = 0; i < 4; i++) nxt[i] = cp[lane + i * 32];
        }
        float4 cv[4];
        float s = 0.f;
        #pragma unroll
        for (int i = 0; i < 4; i++) {
            float4 c = f4ofh(cur4[i]);
            cv[i] = c;
            s += ew[i].x * tanha(c.x) + ew[i].y * tanha(c.y) +
                 ew[i].z * tanha(c.z) + ew[i].w * tanha(c.w);
        }
        #pragma unroll
        for (int o = 16; o; o >>= 1) s += __shfl_xor_sync(0xFFFFFFFFu, s, o);
        float l = s > 0.f ? s : 0.2f * s;
        float aexp = expf(-l);
        den += aexp;
        #pragma unroll
        for (int i = 0; i < 4; i++) {
            acc[i].x = fmaf(aexp, cv[i].x, acc[i].x);
            acc[i].y = fmaf(aexp, cv[i].y, acc[i].y);
            acc[i].z = fmaf(aexp, cv[i].z, acc[i].z);
            acc[i].w = fmaf(aexp, cv[i].w, acc[i].w);
        }
    }

    if (den == 0.f) den = 1e-12f;
    float invden = 1.f / den;
    const uint2* epp = (const uint2*)(Epreh + (size_t)warp * D);
    float4* op = (float4*)(entnew + (size_t)warp * D);
    float nrm = 0.f;
    float4 tv[4];
    #pragma unroll
    for (int i = 0; i < 4; i++) {
        int ii = lane + i * 32;
        float4 ep4 = f4ofh(epp[ii]);
        float4 t;
        float x = acc[i].x * invden; t.x = ep4.x + (x > 0.f ? x : expm1f(x));
        x = acc[i].y * invden;       t.y = ep4.y + (x > 0.f ? x : expm1f(x));
        x = acc[i].z * invden;       t.z = ep4.z + (x > 0.f ? x : expm1f(x));
        x = acc[i].w * invden;       t.w = ep4.w + (x > 0.f ? x : expm1f(x));
        tv[i] = t;
        nrm += t.x * t.x + t.y * t.y + t.z * t.z + t.w * t.w;
    }
    #pragma unroll
    for (int o = 16; o; o >>= 1) nrm += __shfl_xor_sync(0xFFFFFFFFu, nrm, o);
    float inv = 1.f / fmaxf(sqrtf(nrm), 1e-12f);
    #pragma unroll
    for (int i = 0; i < 4; i++) {
        int ii = lane + i * 32;
        float4 t = tv[i];
        op[ii] = make_float4(t.x * inv, t.y * inv, t.z * inv, t.w * inv);
    }
}

// ---------------------------------------------------------------------------
// mma.sync fp16 GEMM: CTA 128x128, 256 threads (8 warps: 4M x 2N, warp 32x64),
// BK=64, 3-stage pipeline, 2 CTAs/SM, fp16 output.
// AMODE 0: A rows streamed via cp.async.
// AMODE 1: A row j = e0h[dst[eidx[j]]] * relh[edge[eidx[j]]], gathered +
//          multiplied in registers one chunk ahead, stored via st.shared.
// ---------------------------------------------------------------------------
#define MM_BM 128
#define MM_BN 128
#define MM_BK 64
#define MM_LD 72
#define MM_STAGES 3
static constexpr int MM_AH = 0;
static constexpr int MM_BH = 128 * MM_LD;                 // 9216 halves
static constexpr int MM_STAGE_H = 2 * 128 * MM_LD;        // 18432 halves
static constexpr int MM_STAGE_BYTES = MM_STAGE_H * 2;     // 36864
static constexpr int MM_SMEM_BYTES = MM_STAGES * MM_STAGE_BYTES; // 110592

template<int AMODE>
__global__ void __launch_bounds__(256, 2)
gemm_mma_kernel(const __half* __restrict__ A, const __half* __restrict__ Bh,
                __half* __restrict__ C, int M, int D,
                const __half* __restrict__ relh, const int* __restrict__ eidx,
                const int* __restrict__ dsts, const int* __restrict__ edges) {
    extern __shared__ __half sh[];
    uint32_t sbase = smem_to_u32(sh);
    int tid = threadIdx.x;
    int lane = tid & 31;
    int warp = tid >> 5;
    int mb = blockIdx.x * MM_BM;
    int nb = blockIdx.y * MM_BN;
    int wm = (warp >> 1) * 32;
    int wn = (warp & 1) * 64;
    const int nch = D / MM_BK;      // 8

    float acc[2][8][4];
    #pragma unroll
    for (int i = 0; i < 2; i++)
        #pragma unroll
        for (int j = 0; j < 8; j++)
            #pragma unroll
            for (int q = 0; q < 4; q++) acc[i][j][q] = 0.f;

    int arow = tid >> 3;            // 0..31; rows arow + i*32
    int achk = (tid & 7) * 8;       // half offset within 64-chunk
    bool apred[4];
    uint32_t aoff[4], roff[4];      // element offsets for gather mode
    size_t abase[4];                // for plain mode
    #pragma unroll
    for (int i = 0; i < 4; i++) {
        int gm = mb + arow + i * 32;
        apred[i] = gm < M;
        if (AMODE == 0) {
            abase[i] = (size_t)(apred[i] ? gm : 0) * D + achk;
        } else {
            int e = apred[i] ? eidx[gm] : 0;
            aoff[i] = (uint32_t)(dsts[e]) * D + achk;
            roff[i] = (uint32_t)(edges[e]) * D + achk;
        }
    }

    uint4 pa[4];                    // gather-mode A prefetch (product)
    auto gpre = [&](int ch) {
        if (AMODE == 1 && ch < nch) {
            int kb = ch * MM_BK;
            #pragma unroll
            for (int i = 0; i < 4; i++) {
                uint4 ea = *(const uint4*)(A + aoff[i] + kb);
                uint4 ra = *(const uint4*)(relh + roff[i] + kb);
                pa[i] = hmul8(ea, ra);
            }
        }
    };
    auto stsA = [&](int ch) {
        if (AMODE == 1 && ch < nch) {
            uint32_t st = sbase + (ch % MM_STAGES) * MM_STAGE_BYTES;
            #pragma unroll
            for (int i = 0; i < 4; i++) {
                int row = arow + i * 32;
                sts16(st + (MM_AH + row * MM_LD + achk) * 2, pa[i]);
            }
        }
    };
    auto stageB = [&](int ch) {
        if (ch < nch) {
            int kb = ch * MM_BK;
            uint32_t st = sbase + (ch % MM_STAGES) * MM_STAGE_BYTES;
            #pragma unroll
            for (int i = 0; i < 4; i++) {
                int row = arow + i * 32;
                if (AMODE == 0)
                    cp16(st + (MM_AH + row * MM_LD + achk) * 2, A + abase[i] + kb, apred[i]);
                size_t go = (size_t)(nb + row) * D + kb + achk;
                cp16(st + (MM_BH + row * MM_LD + achk) * 2, Bh + go, true);
            }
        }
        asm volatile("cp.async.commit_group;" ::: "memory");
    };

    if (AMODE == 1) {
        gpre(0); stsA(0);
        gpre(1); stsA(1);
        gpre(2);
    }
    stageB(0);
    stageB(1);

    int a_r = (lane & 15);
    int a_c = (lane >> 4) << 3;
    int b_r = (lane & 7) + ((lane & 16) >> 1);
    int b_c = (lane & 8);

    for (int ch = 0; ch < nch; ch++) {
        asm volatile("cp.async.wait_group 1;" ::: "memory");
        __syncthreads();
        stageB(ch + 2);
        if (AMODE == 1) {
            stsA(ch + 2);       // from regs prefetched last iteration
            gpre(ch + 3);       // prefetch for next iteration's stsA
        }

        uint32_t stb = sbase + (ch % MM_STAGES) * MM_STAGE_BYTES;
        #pragma unroll
        for (int s16 = 0; s16 < 4; s16++) {
            int k0 = s16 * 16;
            uint32_t ah[2][4], bh[8][2];
            #pragma unroll
            for (int mi = 0; mi < 2; mi++) {
                uint32_t addr = stb + (MM_AH + (wm + mi * 16 + a_r) * MM_LD + k0 + a_c) * 2;
                ldsm4(addr, ah[mi][0], ah[mi][1], ah[mi][2], ah[mi][3]);
            }
            #pragma unroll
            for (int nj = 0; nj < 4; nj++) {
                uint32_t addr = stb + (MM_BH + (wn + nj * 16 + b_r) * MM_LD + k0 + b_c) * 2;
                ldsm4(addr, bh[2 * nj][0], bh[2 * nj][1], bh[2 * nj + 1][0], bh[2 * nj + 1][1]);
            }
            #pragma unroll
            for (int mi = 0; mi < 2; mi++)
                #pragma unroll
                for (int nj = 0; nj < 8; nj++) mma_fp16(acc[mi][nj], ah[mi], bh[nj]);
        }
        __syncthreads();
    }

    #pragma unroll
    for (int mi = 0; mi < 2; mi++) {
        int gm0 = mb + wm + mi * 16 + (lane >> 2);
        int gm1 = gm0 + 8;
        #pragma unroll
        for (int nj = 0; nj < 8; nj++) {
            int gn = nb + wn + nj * 8 + (lane & 3) * 2;
            if (gm0 < M)
                *(uint32_t*)(C + (size_t)gm0 * D + gn) =
                    pkh(__float2half_rn(acc[mi][nj][0]), __float2half_rn(acc[mi][nj][1]));
            if (gm1 < M)
                *(uint32_t*)(C + (size_t)gm1 * D + gn) =
                    pkh(__float2half_rn(acc[mi][nj][2]), __float2half_rn(acc[mi][nj][3]));
        }
    }
}

// ---------------------------------------------------------------------------
// fp32 tiled SGEMM (tiny rel_new GEMM, R=500)
// ---------------------------------------------------------------------------
__global__ void gemm128_plain(const float* __restrict__ A0, const float* __restrict__ W,
                              float* __restrict__ C, int M, int D) {
    constexpr int BM = 128, BN = 128, BK = 16;
    __shared__ float As[BK][BM];
    __shared__ float Bs[BK][BN];
    int tid = threadIdx.x;
    int mb = blockIdx.x * BM;
    int nb = blockIdx.y * BN;
    int tx = tid & 15, ty = tid >> 4;
    float acc[8][8];
    #pragma unroll
    for (int i = 0; i < 8; i++)
        #pragma unroll
        for (int j = 0; j < 8; j++) acc[i][j] = 0.f;
    for (int kb = 0; kb < D; kb += BK) {
        #pragma unroll
        for (int i = 0; i < 2; i++) {
            int q = tid + i * 256;
            int row = q >> 2;
            int kc = (q & 3) << 2;
            int gr = mb + row;
            float4 v = make_float4(0.f, 0.f, 0.f, 0.f);
            if (gr < M) v = *(const float4*)(A0 + (size_t)gr * D + kb + kc);
            As[kc + 0][row] = v.x; As[kc + 1][row] = v.y;
            As[kc + 2][row] = v.z; As[kc + 3][row] = v.w;
        }
        #pragma unroll
        for (int i = 0; i < 2; i++) {
            int q = tid + i * 256;
            int kr = q >> 5;
            int jc = (q & 31) << 2;
            *(float4*)&Bs[kr][jc] = *(const float4*)(W + (size_t)(kb + kr) * D + nb + jc);
        }
        __syncthreads();
        #pragma unroll
        for (int k = 0; k < BK; k++) {
            float a[8], b[8];
            *(float4*)&a[0] = *(const float4*)&As[k][ty * 8];
            *(float4*)&a[4] = *(const float4*)&As[k][ty * 8 + 4];
            *(float4*)&b[0] = *(const float4*)&Bs[k][tx * 8];
            *(float4*)&b[4] = *(const float4*)&Bs[k][tx * 8 + 4];
            #pragma unroll
            for (int i = 0; i < 8; i++)
                #pragma unroll
                for (int j = 0; j < 8; j++)
                    acc[i][j] = fmaf(a[i], b[j], acc[i][j]);
        }
        __syncthreads();
    }
    #pragma unroll
    for (int i = 0; i < 8; i++) {
        int gr = mb + ty * 8 + i;
        if (gr < M) {
            float* cp = C + (size_t)gr * D + nb + tx * 8;
            *(float4*)(cp + 0) = make_float4(acc[i][0], acc[i][1], acc[i][2], acc[i][3]);
            *(float4*)(cp + 4) = make_float4(acc[i][4], acc[i][5], acc[i][6], acc[i][7]);
        }
    }
}

// ---------------------------------------------------------------------------
// Final gather
// ---------------------------------------------------------------------------
__global__ void gather_out(const int* __restrict__ triples, const float* __restrict__ entn,
                           const float* __restrict__ reln, float4* __restrict__ out,
                           int B, int D) {
    int nv = D >> 2;
    int total = B * 3 * nv;
    int i = blockIdx.x * blockDim.x + threadIdx.x;
    int stride = gridDim.x * blockDim.x;
    for (; i < total; i += stride) {
        int d4 = i % nv;
        int bt = i / nv;
        int t = bt % 3;
        int b = bt / 3;
        int idx = triples[b * 3 + t];
        const float4* srcp = (t == 1) ? (const float4*)(reln + (size_t)idx * D)
                                      : (const float4*)(entn + (size_t)idx * D);
        out[i] = srcp[d4];
    }
}

// ---------------------------------------------------------------------------
// Launch: 2-stream fork-join DAG
// ---------------------------------------------------------------------------
extern "C" void kernel_launch(void* const* d_in, const int* in_sizes, int n_in,
                              void* d_out, int out_size) {
    const int*   triples  = (const int*)d_in[0];
    const int*   nodelist = (const int*)d_in[1];
    const int*   edgelist = (const int*)d_in[2];
    const float* ent      = (const float*)d_in[3];
    const float* rel      = (const float*)d_in[4];
    const float* W1       = (const float*)d_in[5];
    const float* Wa       = (const float*)d_in[6];
    const float* g0       = (const float*)d_in[7];
    const float* WE       = (const float*)d_in[8];
    const float* WR       = (const float*)d_in[9];

    int B = in_sizes[0] / 3;
    int E = in_sizes[2];
    int D = in_sizes[6];
    int N = in_sizes[3] / D;
    int R = in_sizes[4] / D;

    float *entn, *reln;
    int *cnt, *off, *cur, *eidx, *bsum;
    __half *Epreh, *Cbaseh, *Cedgeh, *e0h, *egh, *relh, *w1h, *weth;
    cudaGetSymbolAddress((void**)&entn,   g_entn);
    cudaGetSymbolAddress((void**)&reln,   g_reln);
    cudaGetSymbolAddress((void**)&Epreh,  g_Epreh);
    cudaGetSymbolAddress((void**)&Cbaseh, g_Cbaseh);
    cudaGetSymbolAddress((void**)&Cedgeh, g_Cedgeh);
    cudaGetSymbolAddress((void**)&cnt,    g_cnt);
    cudaGetSymbolAddress((void**)&off,    g_off);
    cudaGetSymbolAddress((void**)&cur,    g_cur);
    cudaGetSymbolAddress((void**)&eidx,   g_eidx);
    cudaGetSymbolAddress((void**)&bsum,   g_bsum);
    cudaGetSymbolAddress((void**)&e0h,    g_e0h);
    cudaGetSymbolAddress((void**)&egh,    g_egh);
    cudaGetSymbolAddress((void**)&relh,   g_relh);
    cudaGetSymbolAddress((void**)&w1h,    g_w1h);
    cudaGetSymbolAddress((void**)&weth,   g_weth);

    cudaFuncSetAttribute(gemm_mma_kernel<0>,
                         cudaFuncAttributeMaxDynamicSharedMemorySize, MM_SMEM_BYTES);
    cudaFuncSetAttribute(gemm_mma_kernel<1>,
                         cudaFuncAttributeMaxDynamicSharedMemorySize, MM_SMEM_BYTES);

    int nblk = (N + 1023) / 1024;
    dim3 gN((N + MM_BM - 1) / MM_BM, D / MM_BN);
    dim3 gE2((E + MM_BM - 1) / MM_BM, D / MM_BN);
    dim3 gR((R + 127) / 128, D / 128);
    int total4 = B * 3 * (D >> 2);

    cudaStream_t s1;
    cudaStreamCreateWithFlags(&s1, cudaStreamNonBlocking);
    cudaEvent_t evFork, evNorm, evJoin;
    cudaEventCreateWithFlags(&evFork, cudaEventDisableTiming);
    cudaEventCreateWithFlags(&evNorm, cudaEventDisableTiming);
    cudaEventCreateWithFlags(&evJoin, cudaEventDisableTiming);

    cudaEventRecord(evFork, 0);
    cudaStreamWaitEvent(s1, evFork, 0);

    // s0: normalize + weights, then N-side GEMMs
    normalize_split<<<(N + 7) / 8, 256>>>(ent, g0, e0h, egh, N, D);
    split_weights<<<(D * D + 255) / 256, 256>>>(W1, WE, rel, w1h, weth, relh, D, R * D);
    cudaEventRecord(evNorm, 0);
    gemm_mma_kernel<0><<<gN, 256, MM_SMEM_BYTES>>>(egh, w1h, Cbaseh, N, D,
                                                   nullptr, nullptr, nullptr, nullptr);
    gemm_mma_kernel<0><<<gN, 256, MM_SMEM_BYTES>>>(e0h, weth, Epreh, N, D,
                                                   nullptr, nullptr, nullptr, nullptr);

    // s1: CSR + rel GEMM, then fused-gather Cedge GEMM after evNorm
    zero_int<<<(N + 255) / 256, 256, 0, s1>>>(cnt, N);
    count_deg<<<(E + 255) / 256, 256, 0, s1>>>(nodelist, cnt, E);
    scan1<<<nblk, 1024, 0, s1>>>(cnt, off, bsum, N);
    scan3b<<<(N + 255) / 256, 256, 0, s1>>>(off, cur, bsum, nblk, N, E);
    fill_eidx<<<(E + 255) / 256, 256, 0, s1>>>(nodelist, cur, eidx, E);
    gemm128_plain<<<gR, 256, 0, s1>>>(rel, WR, reln, R, D);
    cudaStreamWaitEvent(s1, evNorm, 0);
    gemm_mma_kernel<1><<<gE2, 256, MM_SMEM_BYTES, s1>>>(e0h, w1h, Cedgeh, E, D,
                                                        relh, eidx, nodelist + E, edgelist);
    cudaEventRecord(evJoin, s1);

    // join: aggregation + output
    cudaStreamWaitEvent(0, evJoin, 0);
    node_aggregate<<<(N + 7) / 8, 256>>>(e0h, Cbaseh, Cedgeh, Epreh, Wa, off, entn, N, D);
    gather_out<<<(total4 + 255) / 256, 256>>>(triples, entn, reln, (float4*)d_out, B, D);
}

// round 17
// speedup vs baseline: 1.0958x; 1.0958x over previous
#include <cuda_runtime.h>
#include <cuda_fp16.h>
#include <math.h>
#include <stdint.h>

// ---------------------------------------------------------------------------
// UPGAT layer.  N=100000, R=500, D=512, E=150000, B=4096.
// GEMMs: fp16 single-pass mma.sync, CTA 128x128, 8 warps (32x64), BK=64,
// 3-stage cp.async, 2 CTAs/SM, fp16 outputs (R14-validated config).
// CSR-ordered Cedge via split_edge; node_aggregate uses tanh.approx.f16x2.
// 2-stream fork-join overlap.
// ---------------------------------------------------------------------------

#define MAX_N 100000
#define MAX_E 150000
#define MAX_R 500
#define MAX_D 512

__device__ float g_entn [(size_t)MAX_N * MAX_D];
__device__ float g_reln [(size_t)MAX_R * MAX_D];

__device__ __half g_Epreh [(size_t)MAX_N * MAX_D];
__device__ __half g_Cbaseh[(size_t)MAX_N * MAX_D];
__device__ __half g_Cedgeh[(size_t)MAX_E * MAX_D];

__device__ int g_cnt [MAX_N];
__device__ int g_off [MAX_N + 1];
__device__ int g_cur [MAX_N];
__device__ int g_eidx[MAX_E];
__device__ int g_bsum[128];

__device__ __half g_e0h[(size_t)MAX_N * MAX_D];
__device__ __half g_egh[(size_t)MAX_N * MAX_D];
__device__ __half g_edh[(size_t)MAX_E * MAX_D];
__device__ __half g_relh[(size_t)MAX_R * MAX_D];
__device__ __half g_w1h[MAX_D * MAX_D];
__device__ __half g_weth[MAX_D * MAX_D];

// ---------------------------------------------------------------------------
// helpers
// ---------------------------------------------------------------------------
__device__ __forceinline__ uint32_t smem_to_u32(const void* smem_ptr) {
    uint32_t addr;
    asm("{ .reg .u64 tmp; cvta.to.shared.u64 tmp, %1; cvt.u32.u64 %0, tmp; }"
        : "=r"(addr) : "l"(smem_ptr));
    return addr;
}
__device__ __forceinline__ void ldsm4(uint32_t addr, uint32_t& r0, uint32_t& r1,
                                      uint32_t& r2, uint32_t& r3) {
    asm volatile("ldmatrix.sync.aligned.m8n8.x4.shared.b16 {%0,%1,%2,%3}, [%4];"
                 : "=r"(r0), "=r"(r1), "=r"(r2), "=r"(r3) : "r"(addr));
}
__device__ __forceinline__ void mma_fp16(float* d, const uint32_t* a, const uint32_t* b) {
    asm volatile(
        "mma.sync.aligned.m16n8k16.row.col.f32.f16.f16.f32 "
        "{%0,%1,%2,%3}, {%4,%5,%6,%7}, {%8,%9}, {%0,%1,%2,%3};"
        : "+f"(d[0]), "+f"(d[1]), "+f"(d[2]), "+f"(d[3])
        : "r"(a[0]), "r"(a[1]), "r"(a[2]), "r"(a[3]), "r"(b[0]), "r"(b[1]));
}
__device__ __forceinline__ void cp16(uint32_t dst, const void* src, bool pred) {
    int sz = pred ? 16 : 0;
    asm volatile("cp.async.cg.shared.global [%0], [%1], 16, %2;"
                 :: "r"(dst), "l"(src), "r"(sz) : "memory");
}
__device__ __forceinline__ uint32_t pkh(__half a, __half b) {
    __half2 t = __halves2half2(a, b);
    return *reinterpret_cast<uint32_t*>(&t);
}
__device__ __forceinline__ uint2 h4(float4 v) {
    return make_uint2(pkh(__float2half_rn(v.x), __float2half_rn(v.y)),
                      pkh(__float2half_rn(v.z), __float2half_rn(v.w)));
}
__device__ __forceinline__ float4 f4ofh(uint2 u) {
    __half2* h2 = (__half2*)&u;
    float2 a = __half22float2(h2[0]);
    float2 b = __half22float2(h2[1]);
    return make_float4(a.x, a.y, b.x, b.y);
}
// packed half2 tanh on 4 halves
__device__ __forceinline__ uint2 htanh4(uint2 u) {
    uint2 r;
    asm("tanh.approx.f16x2 %0, %1;" : "=r"(r.x) : "r"(u.x));
    asm("tanh.approx.f16x2 %0, %1;" : "=r"(r.y) : "r"(u.y));
    return r;
}

// ---------------------------------------------------------------------------
__global__ void zero_int(int* __restrict__ p, int n) {
    int i = blockIdx.x * blockDim.x + threadIdx.x;
    if (i < n) p[i] = 0;
}

__global__ void normalize_split(const float* __restrict__ in, const float* __restrict__ g0,
                                __half* __restrict__ e0h, __half* __restrict__ egh,
                                int M, int D) {
    int warp = (blockIdx.x * blockDim.x + threadIdx.x) >> 5;
    int lane = threadIdx.x & 31;
    if (warp >= M) return;
    const float4* ip = (const float4*)(in + (size_t)warp * D);
    const float4* gp = (const float4*)g0;
    int nv = D >> 2;
    float s = 0.f;
    for (int i = lane; i < nv; i += 32) {
        float4 v = ip[i];
        s += v.x * v.x + v.y * v.y + v.z * v.z + v.w * v.w;
    }
    #pragma unroll
    for (int o = 16; o; o >>= 1) s += __shfl_xor_sync(0xFFFFFFFFu, s, o);
    float inv = 1.f / fmaxf(sqrtf(s), 1e-12f);
    size_t rbase = (size_t)warp * D;
    for (int i = lane; i < nv; i += 32) {
        float4 v = ip[i];
        float4 n = make_float4(v.x * inv, v.y * inv, v.z * inv, v.w * inv);
        *(uint2*)(e0h + rbase + i * 4) = h4(n);
        float4 g = gp[i];
        *(uint2*)(egh + rbase + i * 4) =
            h4(make_float4(n.x * g.x, n.y * g.y, n.z * g.z, n.w * g.w));
    }
}

__global__ void split_edge(const __half* __restrict__ e0h, const __half* __restrict__ relh,
                           const int* __restrict__ dsts, const int* __restrict__ edges,
                           const int* __restrict__ eidx,
                           __half* __restrict__ eh, int E, int D) {
    int warp = (blockIdx.x * blockDim.x + threadIdx.x) >> 5;
    int lane = threadIdx.x & 31;
    if (warp >= E) return;
    int e = eidx[warp];
    int dst = dsts[e];
    int rl = edges[e];
    const uint2* ap = (const uint2*)(e0h + (size_t)dst * D);
    const uint2* gp = (const uint2*)(relh + (size_t)rl * D);
    uint2* op = (uint2*)(eh + (size_t)warp * D);
    int nv = D >> 2;
    for (int i = lane; i < nv; i += 32) {
        uint2 a = ap[i], g = gp[i];
        __half2* ah = (__half2*)&a;
        __half2* gh = (__half2*)&g;
        uint2 r;
        __half2* rh = (__half2*)&r;
        rh[0] = __hmul2(ah[0], gh[0]);
        rh[1] = __hmul2(ah[1], gh[1]);
        op[i] = r;
    }
}

__global__ void split_weights(const float* __restrict__ W1, const float* __restrict__ WE,
                              const float* __restrict__ rel,
                              __half* __restrict__ w1h, __half* __restrict__ weth,
                              __half* __restrict__ relh, int D, int RD) {
    int i = blockIdx.x * blockDim.x + threadIdx.x;
    int tot = D * D;
    if (i < tot) {
        w1h[i] = __float2half_rn(W1[i]);
        int k = i / D, j = i % D;
        weth[(size_t)j * D + k] = __float2half_rn(WE[i]);
    }
    if (i < RD) relh[i] = __float2half_rn(rel[i]);
}

__global__ void count_deg(const int* __restrict__ srcs, int* __restrict__ cnt, int E) {
    int e = blockIdx.x * blockDim.x + threadIdx.x;
    if (e < E) atomicAdd(&cnt[srcs[e]], 1);
}
__global__ void scan1(const int* __restrict__ cnt, int* __restrict__ off,
                      int* __restrict__ bsum, int N) {
    __shared__ int sm[1024];
    int tid = threadIdx.x;
    int i = blockIdx.x * 1024 + tid;
    int v = (i < N) ? cnt[i] : 0;
    sm[tid] = v;
    __syncthreads();
    #pragma unroll
    for (int d = 1; d < 1024; d <<= 1) {
        int t = (tid >= d) ? sm[tid - d] : 0;
        __syncthreads();
        sm[tid] += t;
        __syncthreads();
    }
    if (i < N) off[i] = sm[tid] - v;
    if (tid == 1023) bsum[blockIdx.x] = sm[1023];
}
__global__ void scan3b(int* __restrict__ off, int* __restrict__ cur,
                       const int* __restrict__ bsum, int nblk, int N, int E) {
    __shared__ int sb[128];
    int tid = threadIdx.x;
    if (tid < 128) sb[tid] = (tid < nblk) ? bsum[tid] : 0;
    __syncthreads();
    #pragma unroll
    for (int d = 1; d < 128; d <<= 1) {
        int t = (tid < 128 && tid >= d) ? sb[tid - d] : 0;
        __syncthreads();
        if (tid < 128) sb[tid] += t;
        __syncthreads();
    }
    int i = blockIdx.x * blockDim.x + tid;
    if (i < N) {
        int bi = i >> 10;
        int pre = (bi == 0) ? 0 : sb[bi - 1];
        int o = off[i] + pre;
        off[i] = o;
        cur[i] = o;
    }
    if (i == 0) off[N] = E;
}
__global__ void fill_eidx(const int* __restrict__ srcs, int* __restrict__ cur,
                          int* __restrict__ eidx, int E) {
    int e = blockIdx.x * blockDim.x + threadIdx.x;
    if (e < E) {
        int pos = atomicAdd(&cur[srcs[e]], 1);
        eidx[pos] = e;
    }
}

__global__ void node_aggregate(const __half* __restrict__ e0h, const __half* __restrict__ Cbh,
                               const __half* __restrict__ Ceh, const __half* __restrict__ Epreh,
                               const float* __restrict__ Wa,
                               const int* __restrict__ off,
                               float* __restrict__ entnew, int N, int D) {
    __shared__ float waS[512];
    for (int i = threadIdx.x; i < D; i += blockDim.x) waS[i] = Wa[i];
    __syncthreads();

    int warp = (blockIdx.x * blockDim.x + threadIdx.x) >> 5;
    int lane = threadIdx.x & 31;
    if (warp >= N) return;
    int o0 = off[warp], o1 = off[warp + 1];
    int deg = o1 - o0;

    const uint2* ep = (const uint2*)(e0h + (size_t)warp * D);
    const uint2* cbp = (const uint2*)(Cbh + (size_t)warp * D);
    const float4* wp = (const float4*)waS;

    float4 ew[4], acc[4];
    float sb = 0.f;
    #pragma unroll
    for (int i = 0; i < 4; i++) {
        int ii = lane + i * 32;
        float4 e = f4ofh(ep[ii]);
        float4 w = wp[ii];
        ew[i] = make_float4(e.x * w.x, e.y * w.y, e.z * w.z, e.w * w.w);
        uint2 cu = cbp[ii];
        float4 c = f4ofh(cu);
        acc[i] = c;
        float4 th = f4ofh(htanh4(cu));
        sb += ew[i].x * th.x + ew[i].y * th.y + ew[i].z * th.z + ew[i].w * th.w;
    }
    #pragma unroll
    for (int o = 16; o; o >>= 1) sb += __shfl_xor_sync(0xFFFFFFFFu, sb, o);
    float lb = sb > 0.f ? sb : 0.2f * sb;
    float ab = expf(-lb);
    float coef = (deg > 0) ? ab : 0.f;
    float den = coef;
    #pragma unroll
    for (int i = 0; i < 4; i++) {
        acc[i].x *= coef; acc[i].y *= coef; acc[i].z *= coef; acc[i].w *= coef;
    }

    uint2 nxt[4];
    if (deg > 0) {
        const uint2* cp = (const uint2*)(Ceh + (size_t)o0 * D);
        #pragma unroll
        for (int i = 0; i < 4; i++) nxt[i] = cp[lane + i * 32];
    }
    for (int j = o0; j < o1; j++) {
        uint2 cur4[4];
        #pragma unroll
        for (int i = 0; i < 4; i++) cur4[i] = nxt[i];
        if (j + 1 < o1) {
            const uint2* cp = (const uint2*)(Ceh + (size_t)(j + 1) * D);
            #pragma unroll
            for (int i = 0; i < 4; i++) nxt[i] = cp[lane + i * 32];
        }
        float4 cv[4];
        float s = 0.f;
        #pragma unroll
        for (int i = 0; i < 4; i++) {
            cv[i] = f4ofh(cur4[i]);
            float4 th = f4ofh(htanh4(cur4[i]));
            s += ew[i].x * th.x + ew[i].y * th.y + ew[i].z * th.z + ew[i].w * th.w;
        }
        #pragma unroll
        for (int o = 16; o; o >>= 1) s += __shfl_xor_sync(0xFFFFFFFFu, s, o);
        float l = s > 0.f ? s : 0.2f * s;
        float aexp = expf(-l);
        den += aexp;
        #pragma unroll
        for (int i = 0; i < 4; i++) {
            acc[i].x = fmaf(aexp, cv[i].x, acc[i].x);
            acc[i].y = fmaf(aexp, cv[i].y, acc[i].y);
            acc[i].z = fmaf(aexp, cv[i].z, acc[i].z);
            acc[i].w = fmaf(aexp, cv[i].w, acc[i].w);
        }
    }

    if (den == 0.f) den = 1e-12f;
    float invden = 1.f / den;
    const uint2* epp = (const uint2*)(Epreh + (size_t)warp * D);
    float4* op = (float4*)(entnew + (size_t)warp * D);
    float nrm = 0.f;
    float4 tv[4];
    #pragma unroll
    for (int i = 0; i < 4; i++) {
        int ii = lane + i * 32;
        float4 ep4 = f4ofh(epp[ii]);
        float4 t;
        float x = acc[i].x * invden; t.x = ep4.x + (x > 0.f ? x : expm1f(x));
        x = acc[i].y * invden;       t.y = ep4.y + (x > 0.f ? x : expm1f(x));
        x = acc[i].z * invden;       t.z = ep4.z + (x > 0.f ? x : expm1f(x));
        x = acc[i].w * invden;       t.w = ep4.w + (x > 0.f ? x : expm1f(x));
        tv[i] = t;
        nrm += t.x * t.x + t.y * t.y + t.z * t.z + t.w * t.w;
    }
    #pragma unroll
    for (int o = 16; o; o >>= 1) nrm += __shfl_xor_sync(0xFFFFFFFFu, nrm, o);
    float inv = 1.f / fmaxf(sqrtf(nrm), 1e-12f);
    #pragma unroll
    for (int i = 0; i < 4; i++) {
        int ii = lane + i * 32;
        float4 t = tv[i];
        op[ii] = make_float4(t.x * inv, t.y * inv, t.z * inv, t.w * inv);
    }
}

// ---------------------------------------------------------------------------
// mma.sync fp16 GEMM: CTA 128x128, 256 threads (8 warps: 4M x 2N, warp 32x64),
// BK=64, 3-stage cp.async, 2 CTAs/SM, fp16 output.
// ---------------------------------------------------------------------------
#define MM_BM 128
#define MM_BN 128
#define MM_BK 64
#define MM_LD 72
#define MM_STAGES 3
static constexpr int MM_AH = 0;
static constexpr int MM_BH = 128 * MM_LD;
static constexpr int MM_STAGE_H = 2 * 128 * MM_LD;
static constexpr int MM_STAGE_BYTES = MM_STAGE_H * 2;
static constexpr int MM_SMEM_BYTES = MM_STAGES * MM_STAGE_BYTES;

__global__ void __launch_bounds__(256, 2)
gemm_mma_kernel(const __half* __restrict__ A, const __half* __restrict__ Bh,
                __half* __restrict__ C, int M, int D) {
    extern __shared__ __half sh[];
    uint32_t sbase = smem_to_u32(sh);
    int tid = threadIdx.x;
    int lane = tid & 31;
    int warp = tid >> 5;
    int mb = blockIdx.x * MM_BM;
    int nb = blockIdx.y * MM_BN;
    int wm = (warp >> 1) * 32;
    int wn = (warp & 1) * 64;
    const int nch = D / MM_BK;

    float acc[2][8][4];
    #pragma unroll
    for (int i = 0; i < 2; i++)
        #pragma unroll
        for (int j = 0; j < 8; j++)
            #pragma unroll
            for (int q = 0; q < 4; q++) acc[i][j][q] = 0.f;

    int arow = tid >> 3;
    int achk = (tid & 7) * 8;
    bool apred[4];
    size_t abase[4];
    #pragma unroll
    for (int i = 0; i < 4; i++) {
        int gm = mb + arow + i * 32;
        apred[i] = gm < M;
        abase[i] = (size_t)(apred[i] ? gm : 0) * D + achk;
    }

    auto stage_load = [&](int ch) {
        if (ch < nch) {
            int kb = ch * MM_BK;
            uint32_t st = sbase + (ch % MM_STAGES) * MM_STAGE_BYTES;
            #pragma unroll
            for (int i = 0; i < 4; i++) {
                int row = arow + i * 32;
                cp16(st + (MM_AH + row * MM_LD + achk) * 2, A + abase[i] + kb, apred[i]);
                size_t go = (size_t)(nb + row) * D + kb + achk;
                cp16(st + (MM_BH + row * MM_LD + achk) * 2, Bh + go, true);
            }
        }
        asm volatile("cp.async.commit_group;" ::: "memory");
    };

    stage_load(0);
    stage_load(1);

    int a_r = (lane & 15);
    int a_c = (lane >> 4) << 3;
    int b_r = (lane & 7) + ((lane & 16) >> 1);
    int b_c = (lane & 8);

    for (int ch = 0; ch < nch; ch++) {
        asm volatile("cp.async.wait_group 1;" ::: "memory");
        __syncthreads();
        stage_load(ch + 2);

        uint32_t stb = sbase + (ch % MM_STAGES) * MM_STAGE_BYTES;
        #pragma unroll
        for (int s16 = 0; s16 < 4; s16++) {
            int k0 = s16 * 16;
            uint32_t ah[2][4], bh[8][2];
            #pragma unroll
            for (int mi = 0; mi < 2; mi++) {
                uint32_t addr = stb + (MM_AH + (wm + mi * 16 + a_r) * MM_LD + k0 + a_c) * 2;
                ldsm4(addr, ah[mi][0], ah[mi][1], ah[mi][2], ah[mi][3]);
            }
            #pragma unroll
            for (int nj = 0; nj < 4; nj++) {
                uint32_t addr = stb + (MM_BH + (wn + nj * 16 + b_r) * MM_LD + k0 + b_c) * 2;
                ldsm4(addr, bh[2 * nj][0], bh[2 * nj][1], bh[2 * nj + 1][0], bh[2 * nj + 1][1]);
            }
            #pragma unroll
            for (int mi = 0; mi < 2; mi++)
                #pragma unroll
                for (int nj = 0; nj < 8; nj++) mma_fp16(acc[mi][nj], ah[mi], bh[nj]);
        }
        __syncthreads();
    }

    #pragma unroll
    for (int mi = 0; mi < 2; mi++) {
        int gm0 = mb + wm + mi * 16 + (lane >> 2);
        int gm1 = gm0 + 8;
        #pragma unroll
        for (int nj = 0; nj < 8; nj++) {
            int gn = nb + wn + nj * 8 + (lane & 3) * 2;
            if (gm0 < M)
                *(uint32_t*)(C + (size_t)gm0 * D + gn) =
                    pkh(__float2half_rn(acc[mi][nj][0]), __float2half_rn(acc[mi][nj][1]));
            if (gm1 < M)
                *(uint32_t*)(C + (size_t)gm1 * D + gn) =
                    pkh(__float2half_rn(acc[mi][nj][2]), __float2half_rn(acc[mi][nj][3]));
        }
    }
}

// ---------------------------------------------------------------------------
// fp32 tiled SGEMM (tiny rel_new GEMM, R=500)
// ---------------------------------------------------------------------------
__global__ void gemm128_plain(const float* __restrict__ A0, const float* __restrict__ W,
                              float* __restrict__ C, int M, int D) {
    constexpr int BM = 128, BN = 128, BK = 16;
    __shared__ float As[BK][BM];
    __shared__ float Bs[BK][BN];
    int tid = threadIdx.x;
    int mb = blockIdx.x * BM;
    int nb = blockIdx.y * BN;
    int tx = tid & 15, ty = tid >> 4;
    float acc[8][8];
    #pragma unroll
    for (int i = 0; i < 8; i++)
        #pragma unroll
        for (int j = 0; j < 8; j++) acc[i][j] = 0.f;
    for (int kb = 0; kb < D; kb += BK) {
        #pragma unroll
        for (int i = 0; i < 2; i++) {
            int q = tid + i * 256;
            int row = q >> 2;
            int kc = (q & 3) << 2;
            int gr = mb + row;
            float4 v = make_float4(0.f, 0.f, 0.f, 0.f);
            if (gr < M) v = *(const float4*)(A0 + (size_t)gr * D + kb + kc);
            As[kc + 0][row] = v.x; As[kc + 1][row] = v.y;
            As[kc + 2][row] = v.z; As[kc + 3][row] = v.w;
        }
        #pragma unroll
        for (int i = 0; i < 2; i++) {
            int q = tid + i * 256;
            int kr = q >> 5;
            int jc = (q & 31) << 2;
            *(float4*)&Bs[kr][jc] = *(const float4*)(W + (size_t)(kb + kr) * D + nb + jc);
        }
        __syncthreads();
        #pragma unroll
        for (int k = 0; k < BK; k++) {
            float a[8], b[8];
            *(float4*)&a[0] = *(const float4*)&As[k][ty * 8];
            *(float4*)&a[4] = *(const float4*)&As[k][ty * 8 + 4];
            *(float4*)&b[0] = *(const float4*)&Bs[k][tx * 8];
            *(float4*)&b[4] = *(const float4*)&Bs[k][tx * 8 + 4];
            #pragma unroll
            for (int i = 0; i < 8; i++)
                #pragma unroll
                for (int j = 0; j < 8; j++)
                    acc[i][j] = fmaf(a[i], b[j], acc[i][j]);
        }
        __syncthreads();
    }
    #pragma unroll
    for (int i = 0; i < 8; i++) {
        int gr = mb + ty * 8 + i;
        if (gr < M) {
            float* cp = C + (size_t)gr * D + nb + tx * 8;
            *(float4*)(cp + 0) = make_float4(acc[i][0], acc[i][1], acc[i][2], acc[i][3]);
            *(float4*)(cp + 4) = make_float4(acc[i][4], acc[i][5], acc[i][6], acc[i][7]);
        }
    }
}

// ---------------------------------------------------------------------------
// Final gather
// ---------------------------------------------------------------------------
__global__ void gather_out(const int* __restrict__ triples, const float* __restrict__ entn,
                           const float* __restrict__ reln, float4* __restrict__ out,
                           int B, int D) {
    int nv = D >> 2;
    int total = B * 3 * nv;
    int i = blockIdx.x * blockDim.x + threadIdx.x;
    int stride = gridDim.x * blockDim.x;
    for (; i < total; i += stride) {
        int d4 = i % nv;
        int bt = i / nv;
        int t = bt % 3;
        int b = bt / 3;
        int idx = triples[b * 3 + t];
        const float4* srcp = (t == 1) ? (const float4*)(reln + (size_t)idx * D)
                                      : (const float4*)(entn + (size_t)idx * D);
        out[i] = srcp[d4];
    }
}

// ---------------------------------------------------------------------------
// Launch: 2-stream fork-join DAG
// ---------------------------------------------------------------------------
extern "C" void kernel_launch(void* const* d_in, const int* in_sizes, int n_in,
                              void* d_out, int out_size) {
    const int*   triples  = (const int*)d_in[0];
    const int*   nodelist = (const int*)d_in[1];
    const int*   edgelist = (const int*)d_in[2];
    const float* ent      = (const float*)d_in[3];
    const float* rel      = (const float*)d_in[4];
    const float* W1       = (const float*)d_in[5];
    const float* Wa       = (const float*)d_in[6];
    const float* g0       = (const float*)d_in[7];
    const float* WE       = (const float*)d_in[8];
    const float* WR       = (const float*)d_in[9];

    int B = in_sizes[0] / 3;
    int E = in_sizes[2];
    int D = in_sizes[6];
    int N = in_sizes[3] / D;
    int R = in_sizes[4] / D;

    float *entn, *reln;
    int *cnt, *off, *cur, *eidx, *bsum;
    __half *Epreh, *Cbaseh, *Cedgeh, *e0h, *egh, *edh, *relh, *w1h, *weth;
    cudaGetSymbolAddress((void**)&entn,   g_entn);
    cudaGetSymbolAddress((void**)&reln,   g_reln);
    cudaGetSymbolAddress((void**)&Epreh,  g_Epreh);
    cudaGetSymbolAddress((void**)&Cbaseh, g_Cbaseh);
    cudaGetSymbolAddress((void**)&Cedgeh, g_Cedgeh);
    cudaGetSymbolAddress((void**)&cnt,    g_cnt);
    cudaGetSymbolAddress((void**)&off,    g_off);
    cudaGetSymbolAddress((void**)&cur,    g_cur);
    cudaGetSymbolAddress((void**)&eidx,   g_eidx);
    cudaGetSymbolAddress((void**)&bsum,   g_bsum);
    cudaGetSymbolAddress((void**)&e0h,    g_e0h);
    cudaGetSymbolAddress((void**)&egh,    g_egh);
    cudaGetSymbolAddress((void**)&edh,    g_edh);
    cudaGetSymbolAddress((void**)&relh,   g_relh);
    cudaGetSymbolAddress((void**)&w1h,    g_w1h);
    cudaGetSymbolAddress((void**)&weth,   g_weth);

    cudaFuncSetAttribute(gemm_mma_kernel,
                         cudaFuncAttributeMaxDynamicSharedMemorySize, MM_SMEM_BYTES);

    int nblk = (N + 1023) / 1024;
    dim3 gN((N + MM_BM - 1) / MM_BM, D / MM_BN);
    dim3 gE2((E + MM_BM - 1) / MM_BM, D / MM_BN);
    dim3 gR((R + 127) / 128, D / 128);
    int total4 = B * 3 * (D >> 2);

    cudaStream_t s1;
    cudaStreamCreateWithFlags(&s1, cudaStreamNonBlocking);
    cudaEvent_t evFork, evNorm, evJoin;
    cudaEventCreateWithFlags(&evFork, cudaEventDisableTiming);
    cudaEventCreateWithFlags(&evNorm, cudaEventDisableTiming);
    cudaEventCreateWithFlags(&evJoin, cudaEventDisableTiming);

    cudaEventRecord(evFork, 0);
    cudaStreamWaitEvent(s1, evFork, 0);

    // s0: normalize + weights, then N-side GEMMs
    normalize_split<<<(N + 7) / 8, 256>>>(ent, g0, e0h, egh, N, D);
    split_weights<<<(D * D + 255) / 256, 256>>>(W1, WE, rel, w1h, weth, relh, D, R * D);
    cudaEventRecord(evNorm, 0);
    gemm_mma_kernel<<<gN, 256, MM_SMEM_BYTES>>>(egh, w1h, Cbaseh, N, D);
    gemm_mma_kernel<<<gN, 256, MM_SMEM_BYTES>>>(e0h, weth, Epreh, N, D);

    // s1: CSR + rel GEMM, then edge ops after evNorm
    zero_int<<<(N + 255) / 256, 256, 0, s1>>>(cnt, N);
    count_deg<<<(E + 255) / 256, 256, 0, s1>>>(nodelist, cnt, E);
    scan1<<<nblk, 1024, 0, s1>>>(cnt, off, bsum, N);
    scan3b<<<(N + 255) / 256, 256, 0, s1>>>(off, cur, bsum, nblk, N, E);
    fill_eidx<<<(E + 255) / 256, 256, 0, s1>>>(nodelist, cur, eidx, E);
    gemm128_plain<<<gR, 256, 0, s1>>>(rel, WR, reln, R, D);
    cudaStreamWaitEvent(s1, evNorm, 0);
    split_edge<<<(E + 7) / 8, 256, 0, s1>>>(e0h, relh, nodelist + E, edgelist, eidx, edh, E, D);
    gemm_mma_kernel<<<gE2, 256, MM_SMEM_BYTES, s1>>>(edh, w1h, Cedgeh, E, D);
    cudaEventRecord(evJoin, s1);

    // join: aggregation + output
    cudaStreamWaitEvent(0, evJoin, 0);
    node_aggregate<<<(N + 7) / 8, 256>>>(e0h, Cbaseh, Cedgeh, Epreh, Wa, off, entn, N, D);
    gather_out<<<(total4 + 255) / 256, 256>>>(triples, entn, reln, (float4*)d_out, B, D);
}